// round 15
// baseline (speedup 1.0000x reference)
#include <cuda_runtime.h>
#include <math.h>
typedef unsigned long long ull;
typedef ulonglong2 ull2;

#define NTH 256
#define TST 1024
#define BATCH 1024
#define EPSF 1e-8f

// ---- SMEM layout (float offsets) ----
#define W10O 0        // stride 70 col-major
#define W20O 8960
#define W11O 17920    // stride 130 col-major
#define W21O 34560
#define WOUTO 51200   // 384
#define BA    51584
#define BB    51648
#define C0P   51712   // 70*8 [xn(6)|h(64)]
#define CBD   52272   // 128*8 : L0 gate out; reused for L2 gate out
#define CB2   53296   // 128*8 : L1 gate out
#define STGO  54320   // 2048 : heads partials g*512 + p*128 + jh*2 + e
#define XB    56368   // 48
#define NB    56416   // 8
#define WP    56424   // 192 : wout partials [pair(48)][chunk(4)]
#define SMF   56616   // 226,464 B

__device__ __forceinline__ ull pack2(float lo, float hi){ull r;asm("mov.b64 %0,{%1,%2};":"=l"(r):"f"(lo),"f"(hi));return r;}
__device__ __forceinline__ void unpack2(ull v,float&lo,float&hi){asm("mov.b64 {%0,%1},%2;":"=f"(lo),"=f"(hi):"l"(v));}
__device__ __forceinline__ void ffma2(ull&d,ull a,ull b){asm("fma.rn.f32x2 %0,%1,%2,%0;":"+l"(d):"l"(a),"l"(b));}
__device__ __forceinline__ ull addx2(ull a,ull b){ull r;asm("add.rn.f32x2 %0,%1,%2;":"=l"(r):"l"(a),"l"(b));return r;}
__device__ __forceinline__ ull mulx2(ull a,ull b){ull r;asm("mul.rn.f32x2 %0,%1,%2;":"=l"(r):"l"(a),"l"(b));return r;}
__device__ __forceinline__ ull shflx1(ull v, int m){
    unsigned lo=(unsigned)v, hi=(unsigned)(v>>32);
    lo=__shfl_xor_sync(0xffffffffu,lo,m);
    hi=__shfl_xor_sync(0xffffffffu,hi,m);
    return ((ull)hi<<32)|lo;
}
__device__ __forceinline__ ull tanh2p(ull v){
    float a,b; unpack2(v,a,b);
    return pack2(tanhf(a), tanhf(b));
}

__global__ void __launch_bounds__(NTH, 1)
lmsc_kernel(const float* __restrict__ x, const float* __restrict__ initF,
            const float* __restrict__ w10,const float* __restrict__ b10,
            const float* __restrict__ w20,const float* __restrict__ b20,
            const float* __restrict__ w11,const float* __restrict__ b11,
            const float* __restrict__ w21,const float* __restrict__ b21,
            const float* __restrict__ w12,const float* __restrict__ b12,
            const float* __restrict__ w22,const float* __restrict__ b22,
            const float* __restrict__ wa, const float* __restrict__ ba,
            const float* __restrict__ wb, const float* __restrict__ bb,
            const float* __restrict__ wout,float* __restrict__ out)
{
    extern __shared__ float sm[];
    const int tid = threadIdx.x;
    const int b0 = blockIdx.x * 8;
    const int j2 = tid >> 1, khl = tid & 1;   // butterfly mapping (PROVEN R12/R13)
    const int hm = tid >> 7;                  // heads: 0->wa, 1->wb
    const int kh = (tid >> 6) & 1;            // heads K-half
    const int jh = tid & 63;                  // heads column
    // wout-partials mapping (heads phase, tid<192): pair p=(r,o), chunk c4
    const int wp_p = tid >> 2;                // 0..47 (valid when tid<192)
    const int wp_r = wp_p / 6, wp_o = wp_p - 6*wp_r;
    const int wp_c4 = tid & 3;

    // ---- SMEM init (R13 verbatim) ----
    for (int idx = tid; idx < 70*128; idx += NTH) {
        int k = idx >> 7, jj = idx & 127;
        sm[W10O + jj*70 + k] = w10[idx];
        sm[W20O + jj*70 + k] = w20[idx];
    }
    for (int idx = tid; idx < 128*128; idx += NTH) {
        int k = idx >> 7, jj = idx & 127;
        sm[W11O + jj*130 + k] = w11[idx];
        sm[W21O + jj*130 + k] = w21[idx];
    }
    for (int idx = tid; idx < 384; idx += NTH) sm[WOUTO + idx] = wout[idx];
    if (tid < 64) { sm[BA + tid] = ba[tid]; sm[BB + tid] = bb[tid]; }
    for (int idx = tid; idx < 512; idx += NTH) {
        int r = idx >> 6, jj = idx & 63;
        sm[C0P + (6+jj)*8 + r] = initF[(b0+r)*66 + 2 + jj];
    }

    // ---- per-thread registers (R13 verbatim) ----
    const ull bz0a = khl ? 0ULL : pack2(b10[j2], b10[j2]);
    const ull bz0b = khl ? 0ULL : pack2(b20[j2], b20[j2]);
    const ull bz1a = khl ? 0ULL : pack2(b11[j2], b11[j2]);
    const ull bz1b = khl ? 0ULL : pack2(b21[j2], b21[j2]);
    const ull bz2a = khl ? 0ULL : pack2(b12[j2], b12[j2]);
    const ull bz2b = khl ? 0ULL : pack2(b22[j2], b22[j2]);

    float wl2a[64], wl2b[64];
#pragma unroll
    for (int i = 0; i < 64; i++) {
        wl2a[i] = w12[(2*i+khl)*128 + j2];
        wl2b[i] = w22[(2*i+khl)*128 + j2];
    }
    float whd[64];
    {
        const float* hsrc = hm ? wb : wa;
#pragma unroll
        for (int i = 0; i < 64; i++) whd[i] = hsrc[(kh*64 + i)*64 + jh];
    }

    // ---- x prologue (R13 verbatim) ----
    const int xr = tid / 6, xd = tid - 6*xr;
    float xc = 0.f;
    if (tid < 48) sm[XB + tid] = x[((size_t)(b0+xr)*TST)*6 + xd];
    __syncthreads();
    if (tid < 8) {
        float s = 0.f;
#pragma unroll
        for (int d = 0; d < 6; d++){ float v = sm[XB + tid*6 + d]; s = fmaf(v,v,s); }
        float nrm = sqrtf(s); sm[NB + tid] = nrm;
        float inv = 1.0f/(nrm + EPSF);
#pragma unroll
        for (int d = 0; d < 6; d++) sm[C0P + d*8 + tid] = sm[XB + tid*6 + d]*inv;
    }
    if (tid < 48) xc = x[((size_t)(b0+xr)*TST + 1)*6 + xd];

    float* outs = out;
    float* alph = out + (size_t)BATCH*TST*6;

#pragma unroll 1
    for (int t = 0; t < TST; t++) {
        __syncthreads();                         // A: x/h/norm ready

        {   // L0 butterfly (R13 verbatim)
            const float* w1p = sm + W10O + j2*70 + khl;
            const float* w2p = sm + W20O + j2*70 + khl;
            ull m0=bz0a,m1=bz0a,m2=bz0a,m3=bz0a, n0=bz0b,n1=bz0b,n2=bz0b,n3=bz0b;
#pragma unroll 7
            for (int i = 0; i < 35; i++) {
                const float* ap = sm + C0P + (2*i+khl)*8;
                ull2 qa = *(const ull2*)(ap);
                ull2 qb = *(const ull2*)(ap + 4);
                float w1f = w1p[2*i], w2f = w2p[2*i];
                ull w1 = pack2(w1f,w1f), w2 = pack2(w2f,w2f);
                ffma2(m0,qa.x,w1); ffma2(m1,qa.y,w1); ffma2(m2,qb.x,w1); ffma2(m3,qb.y,w1);
                ffma2(n0,qa.x,w2); ffma2(n1,qa.y,w2); ffma2(n2,qb.x,w2); ffma2(n3,qb.y,w2);
            }
            m0=addx2(m0,shflx1(m0,1)); m1=addx2(m1,shflx1(m1,1));
            m2=addx2(m2,shflx1(m2,1)); m3=addx2(m3,shflx1(m3,1));
            n0=addx2(n0,shflx1(n0,1)); n1=addx2(n1,shflx1(n1,1));
            n2=addx2(n2,shflx1(n2,1)); n3=addx2(n3,shflx1(n3,1));
            ull ga = khl ? mulx2(tanh2p(m2), tanh2p(n2)) : mulx2(tanh2p(m0), tanh2p(n0));
            ull gb = khl ? mulx2(tanh2p(m3), tanh2p(n3)) : mulx2(tanh2p(m1), tanh2p(n1));
            *(ull2*)(sm + CBD + j2*8 + 4*khl) = make_ulonglong2(ga, gb);
        }
        __syncthreads();                         // B

        {   // L1 butterfly (R13 verbatim)
            const float* w1p = sm + W11O + j2*130 + khl;
            const float* w2p = sm + W21O + j2*130 + khl;
            ull m0=bz1a,m1=bz1a,m2=bz1a,m3=bz1a, n0=bz1b,n1=bz1b,n2=bz1b,n3=bz1b;
#pragma unroll 16
            for (int i = 0; i < 64; i++) {
                const float* ap = sm + CBD + (2*i+khl)*8;
                ull2 qa = *(const ull2*)(ap);
                ull2 qb = *(const ull2*)(ap + 4);
                float w1f = w1p[2*i], w2f = w2p[2*i];
                ull w1 = pack2(w1f,w1f), w2 = pack2(w2f,w2f);
                ffma2(m0,qa.x,w1); ffma2(m1,qa.y,w1); ffma2(m2,qb.x,w1); ffma2(m3,qb.y,w1);
                ffma2(n0,qa.x,w2); ffma2(n1,qa.y,w2); ffma2(n2,qb.x,w2); ffma2(n3,qb.y,w2);
            }
            m0=addx2(m0,shflx1(m0,1)); m1=addx2(m1,shflx1(m1,1));
            m2=addx2(m2,shflx1(m2,1)); m3=addx2(m3,shflx1(m3,1));
            n0=addx2(n0,shflx1(n0,1)); n1=addx2(n1,shflx1(n1,1));
            n2=addx2(n2,shflx1(n2,1)); n3=addx2(n3,shflx1(n3,1));
            ull ga = khl ? mulx2(tanh2p(m2), tanh2p(n2)) : mulx2(tanh2p(m0), tanh2p(n0));
            ull gb = khl ? mulx2(tanh2p(m3), tanh2p(n3)) : mulx2(tanh2p(m1), tanh2p(n1));
            *(ull2*)(sm + CB2 + j2*8 + 4*khl) = make_ulonglong2(ga, gb);
        }
        __syncthreads();                         // C

        {   // L2 butterfly (R12/R13 verbatim)
            ull m0=bz2a,m1=bz2a,m2=bz2a,m3=bz2a, n0=bz2b,n1=bz2b,n2=bz2b,n3=bz2b;
#pragma unroll
            for (int i = 0; i < 64; i++) {
                const float* bp = sm + CB2 + (2*i+khl)*8;
                ull2 qa = *(const ull2*)(bp);
                ull2 qb = *(const ull2*)(bp + 4);
                ull w1 = pack2(wl2a[i], wl2a[i]);
                ull w2 = pack2(wl2b[i], wl2b[i]);
                ffma2(m0,qa.x,w1); ffma2(m1,qa.y,w1); ffma2(m2,qb.x,w1); ffma2(m3,qb.y,w1);
                ffma2(n0,qa.x,w2); ffma2(n1,qa.y,w2); ffma2(n2,qb.x,w2); ffma2(n3,qb.y,w2);
            }
            m0=addx2(m0,shflx1(m0,1)); m1=addx2(m1,shflx1(m1,1));
            m2=addx2(m2,shflx1(m2,1)); m3=addx2(m3,shflx1(m3,1));
            n0=addx2(n0,shflx1(n0,1)); n1=addx2(n1,shflx1(n1,1));
            n2=addx2(n2,shflx1(n2,1)); n3=addx2(n3,shflx1(n3,1));
            ull ga = khl ? tanh2p(mulx2(m2,n2)) : tanh2p(mulx2(m0,n0));
            ull gb = khl ? tanh2p(mulx2(m3,n3)) : tanh2p(mulx2(m1,n1));
            *(ull2*)(sm + CBD + j2*8 + 4*khl) = make_ulonglong2(ga, gb);
        }
        __syncthreads();                         // D

        {   // heads (R13 verbatim core) + wout partials for outs(t-1) + x(t+1) stage
            const float* actH = sm + CBD + kh*512;
            ull a0 = 0, a1 = 0, a2 = 0, a3 = 0;
#pragma unroll
            for (int i = 0; i < 64; i++) {
                ull2 u0 = *(const ull2*)(actH + i*8);
                ull2 u1 = *(const ull2*)(actH + i*8 + 4);
                ull w = pack2(whd[i], whd[i]);
                ffma2(a0, u0.x, w); ffma2(a1, u0.y, w);
                ffma2(a2, u1.x, w); ffma2(a3, u1.y, w);
            }
            const int g = hm*2 + kh;
            *(ull*)(sm + STGO + g*512 + 0*128 + jh*2) = a0;
            *(ull*)(sm + STGO + g*512 + 1*128 + jh*2) = a1;
            *(ull*)(sm + STGO + g*512 + 2*128 + jh*2) = a2;
            *(ull*)(sm + STGO + g*512 + 3*128 + jh*2) = a3;

            if (tid < 192) {   // wout partial: C0P still holds h entering this step
                float wacc = 0.f;
#pragma unroll
                for (int i = 0; i < 16; i++) {
                    int k = 4*i + wp_c4;
                    wacc = fmaf(sm[C0P + (6+k)*8 + wp_r], sm[WOUTO + k*6 + wp_o], wacc);
                }
                sm[WP + tid] = wacc;
            }
            if (tid < 48 && t+1 < TST) sm[XB + tid] = xc;   // stage x(t+1)
        }
        __syncthreads();                         // E

        {   // combine (R13 core) + wout finalize(t-1) + norm(t+1) + prefetch x(t+2)
            const int jj = tid & 63;
            const int rg = tid >> 6;
#pragma unroll
            for (int rr = 0; rr < 2; rr++) {
                const int r = rg*2 + rr;
                float pa = sm[STGO + 0*512 + rg*128 + jj*2 + rr]
                         + sm[STGO + 1*512 + rg*128 + jj*2 + rr];
                float pb = sm[STGO + 2*512 + rg*128 + jj*2 + rr]
                         + sm[STGO + 3*512 + rg*128 + jj*2 + rr];
                float alpha = expf(pa + sm[BA + jj]);
                float beta  = tanhf(pb + sm[BB + jj]);
                float hold  = sm[C0P + (6+jj)*8 + r];
                float hn = fmaf(expf(-alpha*sm[NB + r]), hold - beta, beta);
                sm[C0P + (6+jj)*8 + r] = hn;
                alph[((size_t)(b0+r)*TST + t)*64 + jj] = alpha;
            }
            if (tid < 48 && t > 0) {   // finalize outs(t-1)
                float4 wv = *(const float4*)(sm + WP + tid*4);
                outs[((size_t)(b0 + xr)*TST + (t-1))*6 + xd] = (wv.x+wv.y)+(wv.z+wv.w);
            }
            if (tid < 8) {             // norm + xn for t+1 (reads XB staged in heads)
                float s = 0.f;
#pragma unroll
                for (int d = 0; d < 6; d++){ float v = sm[XB + tid*6 + d]; s = fmaf(v,v,s); }
                float nrm = sqrtf(s); sm[NB + tid] = nrm;
                float inv = 1.0f/(nrm + EPSF);
#pragma unroll
                for (int d = 0; d < 6; d++) sm[C0P + d*8 + tid] = sm[XB + tid*6 + d]*inv;
            }
            if (tid < 48 && t+2 < TST)
                xc = x[((size_t)(b0+xr)*TST + (t+2))*6 + xd];
        }
    }

    // epilogue: outs for t = TST-1 (h_new(TST-1) is in C0P)
    __syncthreads();
    if (tid < 48) {
        const int r = tid/6, o = tid - 6*r;
        float acc = 0.f;
#pragma unroll
        for (int k = 0; k < 64; k++)
            acc = fmaf(sm[C0P + (6+k)*8 + r], sm[WOUTO + k*6 + o], acc);
        outs[((size_t)(b0+r)*TST + (TST-1))*6 + o] = acc;
    }
}

extern "C" void kernel_launch(void* const* d_in, const int* in_sizes, int n_in,
                              void* d_out, int out_size)
{
    const float* x    =(const float*)d_in[0];  const float* initF=(const float*)d_in[1];
    const float* w10  =(const float*)d_in[2];  const float* b10  =(const float*)d_in[3];
    const float* w20  =(const float*)d_in[4];  const float* b20  =(const float*)d_in[5];
    const float* w11  =(const float*)d_in[6];  const float* b11  =(const float*)d_in[7];
    const float* w21  =(const float*)d_in[8];  const float* b21  =(const float*)d_in[9];
    const float* w12  =(const float*)d_in[10]; const float* b12  =(const float*)d_in[11];
    const float* w22  =(const float*)d_in[12]; const float* b22  =(const float*)d_in[13];
    const float* wa   =(const float*)d_in[14]; const float* ba   =(const float*)d_in[15];
    const float* wb   =(const float*)d_in[16]; const float* bb   =(const float*)d_in[17];
    const float* wout =(const float*)d_in[18];
    float* out = (float*)d_out;

    const int smem_bytes = SMF * 4;
    cudaFuncSetAttribute(lmsc_kernel, cudaFuncAttributeMaxDynamicSharedMemorySize, smem_bytes);
    lmsc_kernel<<<BATCH/8, NTH, smem_bytes>>>(x, initF, w10,b10,w20,b20, w11,b11,w21,b21,
                                              w12,b12,w22,b22, wa,ba,wb,bb, wout, out);
}

// round 16
// speedup vs baseline: 1.0974x; 1.0974x over previous
#include <cuda_runtime.h>
#include <math.h>
typedef unsigned long long ull;
typedef ulonglong2 ull2;

#define NTH 256
#define TST 1024
#define BATCH 1024
#define EPSF 1e-8f

// ---- SMEM layout (float offsets) ----
#define W10O 0        // stride 70 col-major
#define W20O 8960
#define W11O 17920    // stride 130 col-major
#define W21O 34560
#define WOUTO 51200   // 384
#define BA    51584
#define BB    51648
#define C0P   51712   // 70*8 [xn(6)|h(64)]
#define CBD   52272   // 128*8 : L0 gate out; reused for L2 gate out
#define CB2   53296   // 128*8 : L1 gate out; REUSED in heads for B-partials q=0,1
#define STGO  54320   // 2048 : heads A-partials q*512 + p*128 + jh*2 + e
#define XB    56368   // 48
#define NB    56416   // 8
#define SPARE 56424   // 1024 : heads B-partials q=2,3
#define SMF   57448   // 229,792 B <= 232,448 cap

__device__ __forceinline__ ull pack2(float lo, float hi){ull r;asm("mov.b64 %0,{%1,%2};":"=l"(r):"f"(lo),"f"(hi));return r;}
__device__ __forceinline__ void unpack2(ull v,float&lo,float&hi){asm("mov.b64 {%0,%1},%2;":"=f"(lo),"=f"(hi):"l"(v));}
__device__ __forceinline__ void ffma2(ull&d,ull a,ull b){asm("fma.rn.f32x2 %0,%1,%2,%0;":"+l"(d):"l"(a),"l"(b));}
__device__ __forceinline__ ull addx2(ull a,ull b){ull r;asm("add.rn.f32x2 %0,%1,%2;":"=l"(r):"l"(a),"l"(b));return r;}
__device__ __forceinline__ ull mulx2(ull a,ull b){ull r;asm("mul.rn.f32x2 %0,%1,%2;":"=l"(r):"l"(a),"l"(b));return r;}
__device__ __forceinline__ ull shflx1(ull v, int m){
    unsigned lo=(unsigned)v, hi=(unsigned)(v>>32);
    lo=__shfl_xor_sync(0xffffffffu,lo,m);
    hi=__shfl_xor_sync(0xffffffffu,hi,m);
    return ((ull)hi<<32)|lo;
}
__device__ __forceinline__ ull tanh2p(ull v){
    float a,b; unpack2(v,a,b);
    return pack2(tanhf(a), tanhf(b));
}

__global__ void __launch_bounds__(NTH, 1)
lmsc_kernel(const float* __restrict__ x, const float* __restrict__ initF,
            const float* __restrict__ w10,const float* __restrict__ b10,
            const float* __restrict__ w20,const float* __restrict__ b20,
            const float* __restrict__ w11,const float* __restrict__ b11,
            const float* __restrict__ w21,const float* __restrict__ b21,
            const float* __restrict__ w12,const float* __restrict__ b12,
            const float* __restrict__ w22,const float* __restrict__ b22,
            const float* __restrict__ wa, const float* __restrict__ ba,
            const float* __restrict__ wb, const float* __restrict__ bb,
            const float* __restrict__ wout,float* __restrict__ out)
{
    extern __shared__ float sm[];
    const int tid = threadIdx.x;
    const int b0 = blockIdx.x * 8;
    const int j2 = tid >> 1, khl = tid & 1;   // butterfly mapping (PROVEN)
    const int kq4 = tid >> 6;                 // heads: k-quarter (warp-pair uniform)
    const int jh4 = tid & 63;                 // heads: column

    // ---- SMEM init (R13 verbatim) ----
    for (int idx = tid; idx < 70*128; idx += NTH) {
        int k = idx >> 7, jj = idx & 127;
        sm[W10O + jj*70 + k] = w10[idx];
        sm[W20O + jj*70 + k] = w20[idx];
    }
    for (int idx = tid; idx < 128*128; idx += NTH) {
        int k = idx >> 7, jj = idx & 127;
        sm[W11O + jj*130 + k] = w11[idx];
        sm[W21O + jj*130 + k] = w21[idx];
    }
    for (int idx = tid; idx < 384; idx += NTH) sm[WOUTO + idx] = wout[idx];
    if (tid < 64) { sm[BA + tid] = ba[tid]; sm[BB + tid] = bb[tid]; }
    for (int idx = tid; idx < 512; idx += NTH) {
        int r = idx >> 6, jj = idx & 63;
        sm[C0P + (6+jj)*8 + r] = initF[(b0+r)*66 + 2 + jj];
    }

    // ---- per-thread registers ----
    const ull bz0a = khl ? 0ULL : pack2(b10[j2], b10[j2]);
    const ull bz0b = khl ? 0ULL : pack2(b20[j2], b20[j2]);
    const ull bz1a = khl ? 0ULL : pack2(b11[j2], b11[j2]);
    const ull bz1b = khl ? 0ULL : pack2(b21[j2], b21[j2]);
    const ull bz2a = khl ? 0ULL : pack2(b12[j2], b12[j2]);
    const ull bz2b = khl ? 0ULL : pack2(b22[j2], b22[j2]);

    float wl2a[64], wl2b[64];
#pragma unroll
    for (int i = 0; i < 64; i++) {
        wl2a[i] = w12[(2*i+khl)*128 + j2];
        wl2b[i] = w22[(2*i+khl)*128 + j2];
    }
    float wha[32], whb[32];        // NEW: heads quarter-K, both matrices
#pragma unroll
    for (int i = 0; i < 32; i++) {
        wha[i] = wa[(kq4*32+i)*64 + jh4];
        whb[i] = wb[(kq4*32+i)*64 + jh4];
    }

    // ---- x prologue (R13 verbatim) ----
    const int xr = tid / 6, xd = tid - 6*xr;
    float xc = 0.f;
    if (tid < 48) sm[XB + tid] = x[((size_t)(b0+xr)*TST)*6 + xd];
    __syncthreads();
    if (tid < 8) {
        float s = 0.f;
#pragma unroll
        for (int d = 0; d < 6; d++){ float v = sm[XB + tid*6 + d]; s = fmaf(v,v,s); }
        float nrm = sqrtf(s); sm[NB + tid] = nrm;
        float inv = 1.0f/(nrm + EPSF);
#pragma unroll
        for (int d = 0; d < 6; d++) sm[C0P + d*8 + tid] = sm[XB + tid*6 + d]*inv;
    }
    if (tid < 48) xc = x[((size_t)(b0+xr)*TST + 1)*6 + xd];

    float* outs = out;
    float* alph = out + (size_t)BATCH*TST*6;

#pragma unroll 1
    for (int t = 0; t < TST; t++) {
        __syncthreads();                         // A: x/h/norm ready

        {   // L0 butterfly (R13 verbatim)
            const float* w1p = sm + W10O + j2*70 + khl;
            const float* w2p = sm + W20O + j2*70 + khl;
            ull m0=bz0a,m1=bz0a,m2=bz0a,m3=bz0a, n0=bz0b,n1=bz0b,n2=bz0b,n3=bz0b;
#pragma unroll 7
            for (int i = 0; i < 35; i++) {
                const float* ap = sm + C0P + (2*i+khl)*8;
                ull2 qa = *(const ull2*)(ap);
                ull2 qb = *(const ull2*)(ap + 4);
                float w1f = w1p[2*i], w2f = w2p[2*i];
                ull w1 = pack2(w1f,w1f), w2 = pack2(w2f,w2f);
                ffma2(m0,qa.x,w1); ffma2(m1,qa.y,w1); ffma2(m2,qb.x,w1); ffma2(m3,qb.y,w1);
                ffma2(n0,qa.x,w2); ffma2(n1,qa.y,w2); ffma2(n2,qb.x,w2); ffma2(n3,qb.y,w2);
            }
            m0=addx2(m0,shflx1(m0,1)); m1=addx2(m1,shflx1(m1,1));
            m2=addx2(m2,shflx1(m2,1)); m3=addx2(m3,shflx1(m3,1));
            n0=addx2(n0,shflx1(n0,1)); n1=addx2(n1,shflx1(n1,1));
            n2=addx2(n2,shflx1(n2,1)); n3=addx2(n3,shflx1(n3,1));
            ull ga = khl ? mulx2(tanh2p(m2), tanh2p(n2)) : mulx2(tanh2p(m0), tanh2p(n0));
            ull gb = khl ? mulx2(tanh2p(m3), tanh2p(n3)) : mulx2(tanh2p(m1), tanh2p(n1));
            *(ull2*)(sm + CBD + j2*8 + 4*khl) = make_ulonglong2(ga, gb);
        }
        __syncthreads();                         // B

        {   // L1 butterfly (R13 verbatim)
            const float* w1p = sm + W11O + j2*130 + khl;
            const float* w2p = sm + W21O + j2*130 + khl;
            ull m0=bz1a,m1=bz1a,m2=bz1a,m3=bz1a, n0=bz1b,n1=bz1b,n2=bz1b,n3=bz1b;
#pragma unroll 16
            for (int i = 0; i < 64; i++) {
                const float* ap = sm + CBD + (2*i+khl)*8;
                ull2 qa = *(const ull2*)(ap);
                ull2 qb = *(const ull2*)(ap + 4);
                float w1f = w1p[2*i], w2f = w2p[2*i];
                ull w1 = pack2(w1f,w1f), w2 = pack2(w2f,w2f);
                ffma2(m0,qa.x,w1); ffma2(m1,qa.y,w1); ffma2(m2,qb.x,w1); ffma2(m3,qb.y,w1);
                ffma2(n0,qa.x,w2); ffma2(n1,qa.y,w2); ffma2(n2,qb.x,w2); ffma2(n3,qb.y,w2);
            }
            m0=addx2(m0,shflx1(m0,1)); m1=addx2(m1,shflx1(m1,1));
            m2=addx2(m2,shflx1(m2,1)); m3=addx2(m3,shflx1(m3,1));
            n0=addx2(n0,shflx1(n0,1)); n1=addx2(n1,shflx1(n1,1));
            n2=addx2(n2,shflx1(n2,1)); n3=addx2(n3,shflx1(n3,1));
            ull ga = khl ? mulx2(tanh2p(m2), tanh2p(n2)) : mulx2(tanh2p(m0), tanh2p(n0));
            ull gb = khl ? mulx2(tanh2p(m3), tanh2p(n3)) : mulx2(tanh2p(m1), tanh2p(n1));
            *(ull2*)(sm + CB2 + j2*8 + 4*khl) = make_ulonglong2(ga, gb);
        }
        __syncthreads();                         // C

        {   // L2 butterfly (R13 verbatim)
            ull m0=bz2a,m1=bz2a,m2=bz2a,m3=bz2a, n0=bz2b,n1=bz2b,n2=bz2b,n3=bz2b;
#pragma unroll
            for (int i = 0; i < 64; i++) {
                const float* bp = sm + CB2 + (2*i+khl)*8;
                ull2 qa = *(const ull2*)(bp);
                ull2 qb = *(const ull2*)(bp + 4);
                ull w1 = pack2(wl2a[i], wl2a[i]);
                ull w2 = pack2(wl2b[i], wl2b[i]);
                ffma2(m0,qa.x,w1); ffma2(m1,qa.y,w1); ffma2(m2,qb.x,w1); ffma2(m3,qb.y,w1);
                ffma2(n0,qa.x,w2); ffma2(n1,qa.y,w2); ffma2(n2,qb.x,w2); ffma2(n3,qb.y,w2);
            }
            m0=addx2(m0,shflx1(m0,1)); m1=addx2(m1,shflx1(m1,1));
            m2=addx2(m2,shflx1(m2,1)); m3=addx2(m3,shflx1(m3,1));
            n0=addx2(n0,shflx1(n0,1)); n1=addx2(n1,shflx1(n1,1));
            n2=addx2(n2,shflx1(n2,1)); n3=addx2(n3,shflx1(n3,1));
            ull ga = khl ? tanh2p(mulx2(m2,n2)) : tanh2p(mulx2(m0,n0));
            ull gb = khl ? tanh2p(mulx2(m3,n3)) : tanh2p(mulx2(m1,n1));
            *(ull2*)(sm + CBD + j2*8 + 4*khl) = make_ulonglong2(ga, gb);
        }
        __syncthreads();                         // D

        {   // NEW heads: (kq4, jh4) quarter-K, BOTH mats, acts loaded once
            const float* actH = sm + CBD + kq4*256;      // k = kq4*32 + i
            ull A0=0,A1=0,A2=0,A3=0, B0=0,B1=0,B2=0,B3=0;
#pragma unroll
            for (int i = 0; i < 32; i++) {
                ull2 u0 = *(const ull2*)(actH + i*8);
                ull2 u1 = *(const ull2*)(actH + i*8 + 4);
                ull wad = pack2(wha[i], wha[i]);
                ull wbd = pack2(whb[i], whb[i]);
                ffma2(A0,u0.x,wad); ffma2(A1,u0.y,wad); ffma2(A2,u1.x,wad); ffma2(A3,u1.y,wad);
                ffma2(B0,u0.x,wbd); ffma2(B1,u0.y,wbd); ffma2(B2,u1.x,wbd); ffma2(B3,u1.y,wbd);
            }
            // A-partials -> STGO[kq4]; B-partials -> CB2 (q=0,1) / SPARE (q=2,3)
            float* pA = sm + STGO + kq4*512 + jh4*2;
            float* pB = sm + (kq4 < 2 ? CB2 + kq4*512 : SPARE + (kq4-2)*512) + jh4*2;
            *(ull*)(pA + 0*128) = A0; *(ull*)(pA + 1*128) = A1;
            *(ull*)(pA + 2*128) = A2; *(ull*)(pA + 3*128) = A3;
            *(ull*)(pB + 0*128) = B0; *(ull*)(pB + 1*128) = B1;
            *(ull*)(pB + 2*128) = B2; *(ull*)(pB + 3*128) = B3;
        }
        __syncthreads();                         // E

        {   // combine: sum 4 A-groups and 4 B-groups; h update; alpha out; stage x(t+1)
            const int jj = tid & 63;
            const int rg = tid >> 6;
#pragma unroll
            for (int rr = 0; rr < 2; rr++) {
                const int r = rg*2 + rr;
                const int off = rg*128 + jj*2 + rr;
                float pa = (sm[STGO + 0*512 + off] + sm[STGO + 1*512 + off])
                         + (sm[STGO + 2*512 + off] + sm[STGO + 3*512 + off]);
                float pb = (sm[CB2  + 0*512 + off] + sm[CB2  + 1*512 + off])
                         + (sm[SPARE+ 0*512 + off] + sm[SPARE+ 1*512 + off]);
                float alpha = expf(pa + sm[BA + jj]);
                float beta  = tanhf(pb + sm[BB + jj]);
                float hold  = sm[C0P + (6+jj)*8 + r];
                float hn = fmaf(expf(-alpha*sm[NB + r]), hold - beta, beta);
                sm[C0P + (6+jj)*8 + r] = hn;
                alph[((size_t)(b0+r)*TST + t)*64 + jj] = alpha;
            }
            if (tid < 48 && t+1 < TST) sm[XB + tid] = xc;
        }
        __syncthreads();                         // F

        if (tid < 48) {   // wout (R13 verbatim); prefetch x(t+2)
            const int r = tid/6, o = tid - 6*r;
            float acc = 0.f;
#pragma unroll
            for (int k = 0; k < 64; k++)
                acc = fmaf(sm[C0P + (6+k)*8 + r], sm[WOUTO + k*6 + o], acc);
            outs[((size_t)(b0+r)*TST + t)*6 + o] = acc;
            if (t+2 < TST) xc = x[((size_t)(b0+xr)*TST + (t+2))*6 + xd];
        }
        if (tid < 8) {    // norm + xn for t+1 (R13 verbatim)
            float s = 0.f;
#pragma unroll
            for (int d = 0; d < 6; d++){ float v = sm[XB + tid*6 + d]; s = fmaf(v,v,s); }
            float nrm = sqrtf(s); sm[NB + tid] = nrm;
            float inv = 1.0f/(nrm + EPSF);
#pragma unroll
            for (int d = 0; d < 6; d++) sm[C0P + d*8 + tid] = sm[XB + tid*6 + d]*inv;
        }
    }
}

extern "C" void kernel_launch(void* const* d_in, const int* in_sizes, int n_in,
                              void* d_out, int out_size)
{
    const float* x    =(const float*)d_in[0];  const float* initF=(const float*)d_in[1];
    const float* w10  =(const float*)d_in[2];  const float* b10  =(const float*)d_in[3];
    const float* w20  =(const float*)d_in[4];  const float* b20  =(const float*)d_in[5];
    const float* w11  =(const float*)d_in[6];  const float* b11  =(const float*)d_in[7];
    const float* w21  =(const float*)d_in[8];  const float* b21  =(const float*)d_in[9];
    const float* w12  =(const float*)d_in[10]; const float* b12  =(const float*)d_in[11];
    const float* w22  =(const float*)d_in[12]; const float* b22  =(const float*)d_in[13];
    const float* wa   =(const float*)d_in[14]; const float* ba   =(const float*)d_in[15];
    const float* wb   =(const float*)d_in[16]; const float* bb   =(const float*)d_in[17];
    const float* wout =(const float*)d_in[18];
    float* out = (float*)d_out;

    const int smem_bytes = SMF * 4;
    cudaFuncSetAttribute(lmsc_kernel, cudaFuncAttributeMaxDynamicSharedMemorySize, smem_bytes);
    lmsc_kernel<<<BATCH/8, NTH, smem_bytes>>>(x, initF, w10,b10,w20,b20, w11,b11,w21,b21,
                                              w12,b12,w22,b22, wa,ba,wb,bb, wout, out);
}

// round 17
// speedup vs baseline: 1.1223x; 1.0227x over previous
#include <cuda_runtime.h>
#include <math.h>
typedef unsigned long long ull;
typedef ulonglong2 ull2;

#define NTH 256
#define TST 1024
#define BATCH 1024
#define EPSF 1e-8f

// ---- SMEM layout (float offsets) ----
#define W10O 0        // stride 70 col-major
#define W20O 8960
#define W11O 17920    // stride 130 col-major
#define W21O 34560
#define WOUTO 51200   // 384
#define BA    51584
#define BB    51648
#define C0P   51712   // 70*8 [xn(6)|h(64)]
#define CBD   52272   // 128*8 : L0 gate out; reused for L2 gate out
#define CB2   53296   // 128*8 : L1 gate out
#define STGO  54320   // 2048 : heads partials g*512 + p*128 + jh*2 + e
#define XB    56368   // 48
#define NB    56416   // 8
#define WP    56424   // 192 : wout partials, WP + p*4 + c4
#define SMF   56616   // 226,464 B

__device__ __forceinline__ ull pack2(float lo, float hi){ull r;asm("mov.b64 %0,{%1,%2};":"=l"(r):"f"(lo),"f"(hi));return r;}
__device__ __forceinline__ void unpack2(ull v,float&lo,float&hi){asm("mov.b64 {%0,%1},%2;":"=f"(lo),"=f"(hi):"l"(v));}
__device__ __forceinline__ void ffma2(ull&d,ull a,ull b){asm("fma.rn.f32x2 %0,%1,%2,%0;":"+l"(d):"l"(a),"l"(b));}
__device__ __forceinline__ ull addx2(ull a,ull b){ull r;asm("add.rn.f32x2 %0,%1,%2;":"=l"(r):"l"(a),"l"(b));return r;}
__device__ __forceinline__ ull mulx2(ull a,ull b){ull r;asm("mul.rn.f32x2 %0,%1,%2;":"=l"(r):"l"(a),"l"(b));return r;}
__device__ __forceinline__ ull shflx1(ull v, int m){
    unsigned lo=(unsigned)v, hi=(unsigned)(v>>32);
    lo=__shfl_xor_sync(0xffffffffu,lo,m);
    hi=__shfl_xor_sync(0xffffffffu,hi,m);
    return ((ull)hi<<32)|lo;
}
__device__ __forceinline__ ull tanh2p(ull v){
    float a,b; unpack2(v,a,b);
    return pack2(tanhf(a), tanhf(b));
}

__global__ void __launch_bounds__(NTH, 1)
lmsc_kernel(const float* __restrict__ x, const float* __restrict__ initF,
            const float* __restrict__ w10,const float* __restrict__ b10,
            const float* __restrict__ w20,const float* __restrict__ b20,
            const float* __restrict__ w11,const float* __restrict__ b11,
            const float* __restrict__ w21,const float* __restrict__ b21,
            const float* __restrict__ w12,const float* __restrict__ b12,
            const float* __restrict__ w22,const float* __restrict__ b22,
            const float* __restrict__ wa, const float* __restrict__ ba,
            const float* __restrict__ wb, const float* __restrict__ bb,
            const float* __restrict__ wout,float* __restrict__ out)
{
    extern __shared__ float sm[];
    const int tid = threadIdx.x;
    const int b0 = blockIdx.x * 8;
    const int j2 = tid >> 1, khl = tid & 1;   // butterfly mapping (PROVEN)
    const int hm = tid >> 7;                  // heads: 0->wa, 1->wb
    const int kh = (tid >> 6) & 1;            // heads K-half
    const int jh = tid & 63;                  // heads column
    // wout-partials mapping (tid<192): pair p=(r,o), chunk c4
    const int wp_p = tid >> 2;                // 0..47
    const int wp_r = wp_p / 6, wp_o = wp_p - 6*wp_r;
    const int wp_c4 = tid & 3;

    // ---- SMEM init (R13 verbatim) ----
    for (int idx = tid; idx < 70*128; idx += NTH) {
        int k = idx >> 7, jj = idx & 127;
        sm[W10O + jj*70 + k] = w10[idx];
        sm[W20O + jj*70 + k] = w20[idx];
    }
    for (int idx = tid; idx < 128*128; idx += NTH) {
        int k = idx >> 7, jj = idx & 127;
        sm[W11O + jj*130 + k] = w11[idx];
        sm[W21O + jj*130 + k] = w21[idx];
    }
    for (int idx = tid; idx < 384; idx += NTH) sm[WOUTO + idx] = wout[idx];
    if (tid < 64) { sm[BA + tid] = ba[tid]; sm[BB + tid] = bb[tid]; }
    for (int idx = tid; idx < 512; idx += NTH) {
        int r = idx >> 6, jj = idx & 63;
        sm[C0P + (6+jj)*8 + r] = initF[(b0+r)*66 + 2 + jj];
    }

    // ---- per-thread registers (R13 verbatim) ----
    const ull bz0a = khl ? 0ULL : pack2(b10[j2], b10[j2]);
    const ull bz0b = khl ? 0ULL : pack2(b20[j2], b20[j2]);
    const ull bz1a = khl ? 0ULL : pack2(b11[j2], b11[j2]);
    const ull bz1b = khl ? 0ULL : pack2(b21[j2], b21[j2]);
    const ull bz2a = khl ? 0ULL : pack2(b12[j2], b12[j2]);
    const ull bz2b = khl ? 0ULL : pack2(b22[j2], b22[j2]);

    float wl2a[64], wl2b[64];
#pragma unroll
    for (int i = 0; i < 64; i++) {
        wl2a[i] = w12[(2*i+khl)*128 + j2];
        wl2b[i] = w22[(2*i+khl)*128 + j2];
    }
    float whd[64];
    {
        const float* hsrc = hm ? wb : wa;
#pragma unroll
        for (int i = 0; i < 64; i++) whd[i] = hsrc[(kh*64 + i)*64 + jh];
    }

    // ---- x prologue (R13 verbatim) ----
    const int xr = tid / 6, xd = tid - 6*xr;
    float xc = 0.f;
    if (tid < 48) sm[XB + tid] = x[((size_t)(b0+xr)*TST)*6 + xd];
    __syncthreads();
    if (tid < 8) {
        float s = 0.f;
#pragma unroll
        for (int d = 0; d < 6; d++){ float v = sm[XB + tid*6 + d]; s = fmaf(v,v,s); }
        float nrm = sqrtf(s); sm[NB + tid] = nrm;
        float inv = 1.0f/(nrm + EPSF);
#pragma unroll
        for (int d = 0; d < 6; d++) sm[C0P + d*8 + tid] = sm[XB + tid*6 + d]*inv;
    }
    if (tid < 48) xc = x[((size_t)(b0+xr)*TST + 1)*6 + xd];

    float* outs = out;
    float* alph = out + (size_t)BATCH*TST*6;

#pragma unroll 1
    for (int t = 0; t < TST; t++) {
        __syncthreads();                         // A: x/h/norm ready (and WP(t-1) ready)

        {   // L0 butterfly (R13 verbatim) + finalize outs(t-1) on 48 threads
            if (tid < 48 && t > 0) {
                float4 wv = *(const float4*)(sm + WP + tid*4);
                outs[((size_t)(b0 + xr)*TST + (t-1))*6 + xd] = (wv.x+wv.y)+(wv.z+wv.w);
            }
            const float* w1p = sm + W10O + j2*70 + khl;
            const float* w2p = sm + W20O + j2*70 + khl;
            ull m0=bz0a,m1=bz0a,m2=bz0a,m3=bz0a, n0=bz0b,n1=bz0b,n2=bz0b,n3=bz0b;
#pragma unroll 7
            for (int i = 0; i < 35; i++) {
                const float* ap = sm + C0P + (2*i+khl)*8;
                ull2 qa = *(const ull2*)(ap);
                ull2 qb = *(const ull2*)(ap + 4);
                float w1f = w1p[2*i], w2f = w2p[2*i];
                ull w1 = pack2(w1f,w1f), w2 = pack2(w2f,w2f);
                ffma2(m0,qa.x,w1); ffma2(m1,qa.y,w1); ffma2(m2,qb.x,w1); ffma2(m3,qb.y,w1);
                ffma2(n0,qa.x,w2); ffma2(n1,qa.y,w2); ffma2(n2,qb.x,w2); ffma2(n3,qb.y,w2);
            }
            m0=addx2(m0,shflx1(m0,1)); m1=addx2(m1,shflx1(m1,1));
            m2=addx2(m2,shflx1(m2,1)); m3=addx2(m3,shflx1(m3,1));
            n0=addx2(n0,shflx1(n0,1)); n1=addx2(n1,shflx1(n1,1));
            n2=addx2(n2,shflx1(n2,1)); n3=addx2(n3,shflx1(n3,1));
            ull ga = khl ? mulx2(tanh2p(m2), tanh2p(n2)) : mulx2(tanh2p(m0), tanh2p(n0));
            ull gb = khl ? mulx2(tanh2p(m3), tanh2p(n3)) : mulx2(tanh2p(m1), tanh2p(n1));
            *(ull2*)(sm + CBD + j2*8 + 4*khl) = make_ulonglong2(ga, gb);
        }
        __syncthreads();                         // B

        {   // L1 butterfly (R13 verbatim)
            const float* w1p = sm + W11O + j2*130 + khl;
            const float* w2p = sm + W21O + j2*130 + khl;
            ull m0=bz1a,m1=bz1a,m2=bz1a,m3=bz1a, n0=bz1b,n1=bz1b,n2=bz1b,n3=bz1b;
#pragma unroll 16
            for (int i = 0; i < 64; i++) {
                const float* ap = sm + CBD + (2*i+khl)*8;
                ull2 qa = *(const ull2*)(ap);
                ull2 qb = *(const ull2*)(ap + 4);
                float w1f = w1p[2*i], w2f = w2p[2*i];
                ull w1 = pack2(w1f,w1f), w2 = pack2(w2f,w2f);
                ffma2(m0,qa.x,w1); ffma2(m1,qa.y,w1); ffma2(m2,qb.x,w1); ffma2(m3,qb.y,w1);
                ffma2(n0,qa.x,w2); ffma2(n1,qa.y,w2); ffma2(n2,qb.x,w2); ffma2(n3,qb.y,w2);
            }
            m0=addx2(m0,shflx1(m0,1)); m1=addx2(m1,shflx1(m1,1));
            m2=addx2(m2,shflx1(m2,1)); m3=addx2(m3,shflx1(m3,1));
            n0=addx2(n0,shflx1(n0,1)); n1=addx2(n1,shflx1(n1,1));
            n2=addx2(n2,shflx1(n2,1)); n3=addx2(n3,shflx1(n3,1));
            ull ga = khl ? mulx2(tanh2p(m2), tanh2p(n2)) : mulx2(tanh2p(m0), tanh2p(n0));
            ull gb = khl ? mulx2(tanh2p(m3), tanh2p(n3)) : mulx2(tanh2p(m1), tanh2p(n1));
            *(ull2*)(sm + CB2 + j2*8 + 4*khl) = make_ulonglong2(ga, gb);
        }
        __syncthreads();                         // C

        {   // L2 butterfly (R13 verbatim)
            ull m0=bz2a,m1=bz2a,m2=bz2a,m3=bz2a, n0=bz2b,n1=bz2b,n2=bz2b,n3=bz2b;
#pragma unroll
            for (int i = 0; i < 64; i++) {
                const float* bp = sm + CB2 + (2*i+khl)*8;
                ull2 qa = *(const ull2*)(bp);
                ull2 qb = *(const ull2*)(bp + 4);
                ull w1 = pack2(wl2a[i], wl2a[i]);
                ull w2 = pack2(wl2b[i], wl2b[i]);
                ffma2(m0,qa.x,w1); ffma2(m1,qa.y,w1); ffma2(m2,qb.x,w1); ffma2(m3,qb.y,w1);
                ffma2(n0,qa.x,w2); ffma2(n1,qa.y,w2); ffma2(n2,qb.x,w2); ffma2(n3,qb.y,w2);
            }
            m0=addx2(m0,shflx1(m0,1)); m1=addx2(m1,shflx1(m1,1));
            m2=addx2(m2,shflx1(m2,1)); m3=addx2(m3,shflx1(m3,1));
            n0=addx2(n0,shflx1(n0,1)); n1=addx2(n1,shflx1(n1,1));
            n2=addx2(n2,shflx1(n2,1)); n3=addx2(n3,shflx1(n3,1));
            ull ga = khl ? tanh2p(mulx2(m2,n2)) : tanh2p(mulx2(m0,n0));
            ull gb = khl ? tanh2p(mulx2(m3,n3)) : tanh2p(mulx2(m1,n1));
            *(ull2*)(sm + CBD + j2*8 + 4*khl) = make_ulonglong2(ga, gb);
        }
        __syncthreads();                         // D

        {   // heads (R13 verbatim): split-K, reg weights -> STGO compact
            const float* actH = sm + CBD + kh*512;
            ull a0 = 0, a1 = 0, a2 = 0, a3 = 0;
#pragma unroll
            for (int i = 0; i < 64; i++) {
                ull2 u0 = *(const ull2*)(actH + i*8);
                ull2 u1 = *(const ull2*)(actH + i*8 + 4);
                ull w = pack2(whd[i], whd[i]);
                ffma2(a0, u0.x, w); ffma2(a1, u0.y, w);
                ffma2(a2, u1.x, w); ffma2(a3, u1.y, w);
            }
            const int g = hm*2 + kh;
            *(ull*)(sm + STGO + g*512 + 0*128 + jh*2) = a0;
            *(ull*)(sm + STGO + g*512 + 1*128 + jh*2) = a1;
            *(ull*)(sm + STGO + g*512 + 2*128 + jh*2) = a2;
            *(ull*)(sm + STGO + g*512 + 3*128 + jh*2) = a3;
        }
        __syncthreads();                         // E

        {   // combine (R13 verbatim): alpha/beta, h update, alpha out; stage x(t+1)
            const int jj = tid & 63;
            const int rg = tid >> 6;
#pragma unroll
            for (int rr = 0; rr < 2; rr++) {
                const int r = rg*2 + rr;
                float pa = sm[STGO + 0*512 + rg*128 + jj*2 + rr]
                         + sm[STGO + 1*512 + rg*128 + jj*2 + rr];
                float pb = sm[STGO + 2*512 + rg*128 + jj*2 + rr]
                         + sm[STGO + 3*512 + rg*128 + jj*2 + rr];
                float alpha = expf(pa + sm[BA + jj]);
                float beta  = tanhf(pb + sm[BB + jj]);
                float hold  = sm[C0P + (6+jj)*8 + r];
                float hn = fmaf(expf(-alpha*sm[NB + r]), hold - beta, beta);
                sm[C0P + (6+jj)*8 + r] = hn;
                alph[((size_t)(b0+r)*TST + t)*64 + jj] = alpha;
            }
            if (tid < 48 && t+1 < TST) sm[XB + tid] = xc;
        }
        __syncthreads();                         // F: h_new ready

        {   // wout PARTIALS over 192 threads; norm(t+1); prefetch x(t+2)
            if (tid < 192) {
                float wacc = 0.f;
#pragma unroll
                for (int i = 0; i < 16; i++) {
                    int k = 4*i + wp_c4;
                    wacc = fmaf(sm[C0P + (6+k)*8 + wp_r], sm[WOUTO + k*6 + wp_o], wacc);
                }
                sm[WP + tid] = wacc;
            }
            if (tid < 48 && t+2 < TST)
                xc = x[((size_t)(b0+xr)*TST + (t+2))*6 + xd];
            if (tid < 8) {    // norm + xn for t+1
                float s = 0.f;
#pragma unroll
                for (int d = 0; d < 6; d++){ float v = sm[XB + tid*6 + d]; s = fmaf(v,v,s); }
                float nrm = sqrtf(s); sm[NB + tid] = nrm;
                float inv = 1.0f/(nrm + EPSF);
#pragma unroll
                for (int d = 0; d < 6; d++) sm[C0P + d*8 + tid] = sm[XB + tid*6 + d]*inv;
            }
        }
    }

    // epilogue: finalize outs(TST-1) from WP
    __syncthreads();
    if (tid < 48) {
        float4 wv = *(const float4*)(sm + WP + tid*4);
        outs[((size_t)(b0 + xr)*TST + (TST-1))*6 + xd] = (wv.x+wv.y)+(wv.z+wv.w);
    }
}

extern "C" void kernel_launch(void* const* d_in, const int* in_sizes, int n_in,
                              void* d_out, int out_size)
{
    const float* x    =(const float*)d_in[0];  const float* initF=(const float*)d_in[1];
    const float* w10  =(const float*)d_in[2];  const float* b10  =(const float*)d_in[3];
    const float* w20  =(const float*)d_in[4];  const float* b20  =(const float*)d_in[5];
    const float* w11  =(const float*)d_in[6];  const float* b11  =(const float*)d_in[7];
    const float* w21  =(const float*)d_in[8];  const float* b21  =(const float*)d_in[9];
    const float* w12  =(const float*)d_in[10]; const float* b12  =(const float*)d_in[11];
    const float* w22  =(const float*)d_in[12]; const float* b22  =(const float*)d_in[13];
    const float* wa   =(const float*)d_in[14]; const float* ba   =(const float*)d_in[15];
    const float* wb   =(const float*)d_in[16]; const float* bb   =(const float*)d_in[17];
    const float* wout =(const float*)d_in[18];
    float* out = (float*)d_out;

    const int smem_bytes = SMF * 4;
    cudaFuncSetAttribute(lmsc_kernel, cudaFuncAttributeMaxDynamicSharedMemorySize, smem_bytes);
    lmsc_kernel<<<BATCH/8, NTH, smem_bytes>>>(x, initF, w10,b10,w20,b20, w11,b11,w21,b21,
                                              w12,b12,w22,b22, wa,ba,wb,bb, wout, out);
}